// round 2
// baseline (speedup 1.0000x reference)
#include <cuda_runtime.h>
#include <math.h>

// Problem constants
#define BB     4
#define SEQ    2048
#define DMODEL 1024
#define NH     16
#define DEPTH  64
#define MROWS  (BB*SEQ)   // 8192

// Scratch (static __device__ arrays — allocation-free per harness rules)
// Q/K/V in [B,H,S,DEPTH] layout, attn in [B,S,D] layout.
__device__ float g_q[BB*NH*SEQ*DEPTH];
__device__ float g_k[BB*NH*SEQ*DEPTH];
__device__ float g_v[BB*NH*SEQ*DEPTH];
__device__ float g_attn[MROWS*DMODEL];

// ---------------------------------------------------------------------------
// SGEMM: C[m,n] = scale * sum_k A[m,k] * W[n,k]   (A:[M,1024], W:[1024,1024])
// LAYOUT 0: C row-major [M,1024] (plain)
// LAYOUT 1: C scattered to head-split [B,H,S,DEPTH]
// BM=BN=128, BK=8 double-buffered, 256 threads, 8x8 microtile.
// ---------------------------------------------------------------------------
template <int LAYOUT>
__global__ __launch_bounds__(256) void sgemm_nt(const float* __restrict__ A,
                                                const float* __restrict__ W,
                                                float* __restrict__ C,
                                                float scale)
{
    const int K = 1024;
    const int N = 1024;
    __shared__ float As[2][8][132];   // [buf][k][m], padded
    __shared__ float Bs[2][8][132];   // [buf][k][n], padded

    const int tid = threadIdx.x;
    const int m0 = blockIdx.y * 128;
    const int n0 = blockIdx.x * 128;
    const int tm = (tid >> 4) * 8;    // 0..120
    const int tn = (tid & 15) * 8;    // 0..120

    // load mapping: 256 threads x 1 float4 per operand per stage (128 rows x 8 cols)
    const int lrow = tid >> 1;        // 0..127
    const int lc4  = (tid & 1) * 4;   // 0 or 4

    float acc[8][8];
    #pragma unroll
    for (int i = 0; i < 8; i++)
        #pragma unroll
        for (int j = 0; j < 8; j++) acc[i][j] = 0.f;

    // preload stage 0
    {
        float4 av = *(const float4*)&A[(size_t)(m0 + lrow) * K + lc4];
        float4 wv = *(const float4*)&W[(size_t)(n0 + lrow) * K + lc4];
        As[0][lc4 + 0][lrow] = av.x;
        As[0][lc4 + 1][lrow] = av.y;
        As[0][lc4 + 2][lrow] = av.z;
        As[0][lc4 + 3][lrow] = av.w;
        Bs[0][lc4 + 0][lrow] = wv.x;
        Bs[0][lc4 + 1][lrow] = wv.y;
        Bs[0][lc4 + 2][lrow] = wv.z;
        Bs[0][lc4 + 3][lrow] = wv.w;
    }
    __syncthreads();

    int buf = 0;
    for (int k0 = 0; k0 < K; k0 += 8) {
        // prefetch next stage into registers (hidden behind compute)
        float4 anx, wnx;
        const bool has_next = (k0 + 8) < K;
        if (has_next) {
            anx = *(const float4*)&A[(size_t)(m0 + lrow) * K + (k0 + 8) + lc4];
            wnx = *(const float4*)&W[(size_t)(n0 + lrow) * K + (k0 + 8) + lc4];
        }

        // compute current stage
        #pragma unroll
        for (int k = 0; k < 8; k++) {
            float a[8], b[8];
            *(float4*)&a[0] = *(const float4*)&As[buf][k][tm];
            *(float4*)&a[4] = *(const float4*)&As[buf][k][tm + 4];
            *(float4*)&b[0] = *(const float4*)&Bs[buf][k][tn];
            *(float4*)&b[4] = *(const float4*)&Bs[buf][k][tn + 4];
            #pragma unroll
            for (int i = 0; i < 8; i++)
                #pragma unroll
                for (int j = 0; j < 8; j++)
                    acc[i][j] = fmaf(a[i], b[j], acc[i][j]);
        }

        // commit prefetched stage to the alternate buffer
        if (has_next) {
            const int nb = buf ^ 1;
            As[nb][lc4 + 0][lrow] = anx.x;
            As[nb][lc4 + 1][lrow] = anx.y;
            As[nb][lc4 + 2][lrow] = anx.z;
            As[nb][lc4 + 3][lrow] = anx.w;
            Bs[nb][lc4 + 0][lrow] = wnx.x;
            Bs[nb][lc4 + 1][lrow] = wnx.y;
            Bs[nb][lc4 + 2][lrow] = wnx.z;
            Bs[nb][lc4 + 3][lrow] = wnx.w;
        }
        __syncthreads();
        buf ^= 1;
    }

    // epilogue
    #pragma unroll
    for (int i = 0; i < 8; i++) {
        int m = m0 + tm + i;
        #pragma unroll
        for (int jj = 0; jj < 8; jj += 4) {
            float4 v;
            v.x = acc[i][jj + 0] * scale;
            v.y = acc[i][jj + 1] * scale;
            v.z = acc[i][jj + 2] * scale;
            v.w = acc[i][jj + 3] * scale;
            int n = n0 + tn + jj;
            if (LAYOUT == 0) {
                *(float4*)&C[(size_t)m * N + n] = v;
            } else {
                // head-split scatter: [B,H,S,DEPTH]
                int b = m >> 11;          // /SEQ
                int s = m & (SEQ - 1);
                int h = n >> 6;           // /DEPTH
                int d = n & (DEPTH - 1);  // group of 4 stays within one head
                *(float4*)&C[(((size_t)(b * NH + h)) * SEQ + s) * DEPTH + d] = v;
            }
        }
    }
}

// ---------------------------------------------------------------------------
// Flash attention (fp32, online softmax).
// Block: (bh, q-tile). Br=128 q rows, Bc=64 kv rows, depth=64.
// 256 threads as 16x16; microtile 8 rows x 4 cols.
// grid.x = B*H (so all 64 (b,h) of a q-tile run adjacently -> bias L2 reuse)
// ---------------------------------------------------------------------------
__global__ __launch_bounds__(256) void flash_kernel(const float* __restrict__ bias)
{
    extern __shared__ float sm[];
    // Qt[d][r] 64x132, Kt[d][c] 64x68, Vs[k][d] 64x68, Pt[k][r] 64x132
    float* Qt = sm;                    // 64*132 = 8448
    float* Kt = Qt + 64 * 132;         // 64*68  = 4352
    float* Vs = Kt + 64 * 68;          // 64*68  = 4352
    float* Pt = Vs + 64 * 68;          // 64*132 = 8448

    const int bh = blockIdx.x;         // 0..63
    const int q0 = blockIdx.y * 128;   // q-tile base
    const int b  = bh >> 4;
    const int h  = bh & 15;

    const float* qbase = g_q + (size_t)bh * SEQ * DEPTH;
    const float* kbase = g_k + (size_t)bh * SEQ * DEPTH;
    const float* vbase = g_v + (size_t)bh * SEQ * DEPTH;

    const int tid = threadIdx.x;
    const int tx = tid & 15;
    const int ty = tid >> 4;
    const int r0 = ty * 8;             // my q rows
    const int c0 = tx * 4;             // my kv cols (S gemm) / depth cols (PV)

    // Load Q tile (128 rows x 64 cols), transposed into Qt[d][r]
    #pragma unroll
    for (int i = 0; i < 8; i++) {
        int slot = tid + i * 256;          // 0..2047
        int row = slot >> 4;               // 0..127
        int c4  = (slot & 15) * 4;         // 0..60
        float4 v = *(const float4*)&qbase[(size_t)(q0 + row) * DEPTH + c4];
        Qt[(c4 + 0) * 132 + row] = v.x;
        Qt[(c4 + 1) * 132 + row] = v.y;
        Qt[(c4 + 2) * 132 + row] = v.z;
        Qt[(c4 + 3) * 132 + row] = v.w;
    }

    float o[8][4];
    float mrow[8], lrow[8];
    #pragma unroll
    for (int i = 0; i < 8; i++) {
        mrow[i] = -INFINITY;
        lrow[i] = 0.f;
        #pragma unroll
        for (int j = 0; j < 4; j++) o[i][j] = 0.f;
    }

    for (int k0 = 0; k0 < SEQ; k0 += 64) {
        __syncthreads();   // protect Kt/Vs/Pt from previous iteration readers

        // Load K tile (transposed) and V tile (natural): 64x64 each
        #pragma unroll
        for (int i = 0; i < 4; i++) {
            int slot = tid + i * 256;       // 0..1023
            int row = slot >> 4;            // 0..63
            int c4  = (slot & 15) * 4;
            float4 kv = *(const float4*)&kbase[(size_t)(k0 + row) * DEPTH + c4];
            Kt[(c4 + 0) * 68 + row] = kv.x;
            Kt[(c4 + 1) * 68 + row] = kv.y;
            Kt[(c4 + 2) * 68 + row] = kv.z;
            Kt[(c4 + 3) * 68 + row] = kv.w;
            float4 vv = *(const float4*)&vbase[(size_t)(k0 + row) * DEPTH + c4];
            *(float4*)&Vs[row * 68 + c4] = vv;
        }
        __syncthreads();

        // S = Q K^T (128x64), accumulate over depth
        float s[8][4];
        #pragma unroll
        for (int i = 0; i < 8; i++)
            #pragma unroll
            for (int j = 0; j < 4; j++) s[i][j] = 0.f;

        #pragma unroll
        for (int d = 0; d < 64; d++) {
            float a[8], kk[4];
            *(float4*)&a[0] = *(const float4*)&Qt[d * 132 + r0];
            *(float4*)&a[4] = *(const float4*)&Qt[d * 132 + r0 + 4];
            *(float4*)&kk[0] = *(const float4*)&Kt[d * 68 + c0];
            #pragma unroll
            for (int i = 0; i < 8; i++)
                #pragma unroll
                for (int j = 0; j < 4; j++)
                    s[i][j] = fmaf(a[i], kk[j], s[i][j]);
        }

        // + bias (global read; L2-resident because the 64 (b,h) blocks of this
        //   q-tile are adjacent in the grid)
        #pragma unroll
        for (int i = 0; i < 8; i++) {
            float4 bv = *(const float4*)&bias[(size_t)(q0 + r0 + i) * SEQ + k0 + c0];
            s[i][0] += bv.x; s[i][1] += bv.y; s[i][2] += bv.z; s[i][3] += bv.w;
        }

        // Online softmax update (row reductions over the 16 tx lanes)
        #pragma unroll
        for (int i = 0; i < 8; i++) {
            float tmax = s[i][0];
            tmax = fmaxf(tmax, s[i][1]);
            tmax = fmaxf(tmax, s[i][2]);
            tmax = fmaxf(tmax, s[i][3]);
            #pragma unroll
            for (int off = 1; off < 16; off <<= 1)
                tmax = fmaxf(tmax, __shfl_xor_sync(0xffffffffu, tmax, off));
            float mnew = fmaxf(mrow[i], tmax);
            float corr = __expf(mrow[i] - mnew);
            float rs = 0.f;
            #pragma unroll
            for (int j = 0; j < 4; j++) {
                s[i][j] = __expf(s[i][j] - mnew);
                rs += s[i][j];
            }
            #pragma unroll
            for (int off = 1; off < 16; off <<= 1)
                rs += __shfl_xor_sync(0xffffffffu, rs, off);
            lrow[i] = lrow[i] * corr + rs;
            mrow[i] = mnew;
            #pragma unroll
            for (int j = 0; j < 4; j++) o[i][j] *= corr;
            // store P transposed: Pt[kv][r]
            #pragma unroll
            for (int j = 0; j < 4; j++)
                Pt[(c0 + j) * 132 + r0 + i] = s[i][j];
        }
        __syncthreads();

        // O += P V  (128 x 64)
        #pragma unroll
        for (int k = 0; k < 64; k++) {
            float p[8], vv[4];
            *(float4*)&p[0] = *(const float4*)&Pt[k * 132 + r0];
            *(float4*)&p[4] = *(const float4*)&Pt[k * 132 + r0 + 4];
            *(float4*)&vv[0] = *(const float4*)&Vs[k * 68 + c0];
            #pragma unroll
            for (int i = 0; i < 8; i++)
                #pragma unroll
                for (int j = 0; j < 4; j++)
                    o[i][j] = fmaf(p[i], vv[j], o[i][j]);
        }
    }

    // Epilogue: normalize and write attn in [B,S,D] layout (d = h*64 + c0+j)
    #pragma unroll
    for (int i = 0; i < 8; i++) {
        float inv = 1.f / lrow[i];
        float4 v;
        v.x = o[i][0] * inv;
        v.y = o[i][1] * inv;
        v.z = o[i][2] * inv;
        v.w = o[i][3] * inv;
        *(float4*)&g_attn[((size_t)b * SEQ + q0 + r0 + i) * DMODEL + h * DEPTH + c0] = v;
    }
}

// ---------------------------------------------------------------------------
// Launch
// ---------------------------------------------------------------------------
extern "C" void kernel_launch(void* const* d_in, const int* in_sizes, int n_in,
                              void* d_out, int out_size)
{
    const float* x    = (const float*)d_in[0];
    const float* y    = (const float*)d_in[1];
    const float* bias = (const float*)d_in[2];
    const float* Wq   = (const float*)d_in[3];
    const float* Wk   = (const float*)d_in[4];
    const float* Wv   = (const float*)d_in[5];
    const float* Wo   = (const float*)d_in[6];
    float* out = (float*)d_out;

    float* dq; cudaGetSymbolAddress((void**)&dq, g_q);
    float* dk; cudaGetSymbolAddress((void**)&dk, g_k);
    float* dv; cudaGetSymbolAddress((void**)&dv, g_v);
    float* da; cudaGetSymbolAddress((void**)&da, g_attn);

    const int flash_smem = (64 * 132 + 64 * 68 + 64 * 68 + 64 * 132) * (int)sizeof(float); // 102400
    cudaFuncSetAttribute(flash_kernel, cudaFuncAttributeMaxDynamicSharedMemorySize, flash_smem);

    dim3 gblk(256);
    dim3 ggrid(DMODEL / 128, MROWS / 128);   // (8, 64)

    const float qscale = 0.125f;  // DEPTH^-0.5 = 64^-0.5

    // Projections (head-split layout)
    sgemm_nt<1><<<ggrid, gblk>>>(x, Wq, dq, qscale);
    sgemm_nt<1><<<ggrid, gblk>>>(y, Wk, dk, 1.0f);
    sgemm_nt<1><<<ggrid, gblk>>>(y, Wv, dv, 1.0f);

    // Fused attention: grid.x = B*H (bias reuse), grid.y = q-tiles
    dim3 fgrid(BB * NH, SEQ / 128);          // (64, 16)
    flash_kernel<<<fgrid, dim3(256), flash_smem>>>(bias);

    // Output projection (plain layout -> d_out)
    sgemm_nt<0><<<ggrid, gblk>>>(da, Wo, out, 1.0f);
}

// round 6
// speedup vs baseline: 1.4397x; 1.4397x over previous
#include <cuda_runtime.h>
#include <cuda_bf16.h>
#include <math.h>
#include <stdint.h>

// Problem constants
#define BB     4
#define SEQ    2048
#define DMODEL 1024
#define NH     16
#define DEPTH  64
#define MROWS  (BB*SEQ)   // 8192

// ---------------------------------------------------------------------------
// Scratch (static __device__ arrays — allocation-free per harness rules)
// ---------------------------------------------------------------------------
__device__ float g_q[BB*NH*SEQ*DEPTH];
__device__ float g_k[BB*NH*SEQ*DEPTH];
__device__ float g_v[BB*NH*SEQ*DEPTH];
__device__ float g_attn[MROWS*DMODEL];

// bf16 hi/lo scratch (ushort-typed)
__device__ unsigned short g_xh[MROWS*DMODEL], g_xl[MROWS*DMODEL];
__device__ unsigned short g_yh[MROWS*DMODEL], g_yl[MROWS*DMODEL];
__device__ unsigned short g_ah[MROWS*DMODEL], g_al[MROWS*DMODEL];
__device__ unsigned short g_wqh[DMODEL*DMODEL], g_wql[DMODEL*DMODEL];
__device__ unsigned short g_wkh[DMODEL*DMODEL], g_wkl[DMODEL*DMODEL];
__device__ unsigned short g_wvh[DMODEL*DMODEL], g_wvl[DMODEL*DMODEL];
__device__ unsigned short g_woh[DMODEL*DMODEL], g_wol[DMODEL*DMODEL];

// ---------------------------------------------------------------------------
// Baseline-PTX helpers (no tcgen05 — compute_103 target!)
// ---------------------------------------------------------------------------
__device__ __forceinline__ uint32_t smem_u32(const void* p) {
    uint32_t r;
    asm("{ .reg .u64 t; cvta.to.shared.u64 t, %1; cvt.u32.u64 %0, t; }"
        : "=r"(r) : "l"(p));
    return r;
}

__device__ __forceinline__ void cp_async16(uint32_t saddr, const void* gaddr) {
    asm volatile("cp.async.cg.shared.global [%0], [%1], 16;"
                 :: "r"(saddr), "l"(gaddr) : "memory");
}
__device__ __forceinline__ void cp_commit() {
    asm volatile("cp.async.commit_group;" ::: "memory");
}
template <int N>
__device__ __forceinline__ void cp_wait() {
    asm volatile("cp.async.wait_group %0;" :: "n"(N) : "memory");
}

__device__ __forceinline__ void ldmx4(uint32_t* r, uint32_t a) {
    asm volatile("ldmatrix.sync.aligned.m8n8.x4.shared.b16 {%0,%1,%2,%3}, [%4];"
                 : "=r"(r[0]), "=r"(r[1]), "=r"(r[2]), "=r"(r[3]) : "r"(a));
}
__device__ __forceinline__ void ldmx2(uint32_t* r, uint32_t a) {
    asm volatile("ldmatrix.sync.aligned.m8n8.x2.shared.b16 {%0,%1}, [%2];"
                 : "=r"(r[0]), "=r"(r[1]) : "r"(a));
}

__device__ __forceinline__ void mma16816(float* d, const uint32_t* a, const uint32_t* b) {
    asm volatile(
        "mma.sync.aligned.m16n8k16.row.col.f32.bf16.bf16.f32 "
        "{%0,%1,%2,%3}, {%4,%5,%6,%7}, {%8,%9}, {%0,%1,%2,%3};"
        : "+f"(d[0]), "+f"(d[1]), "+f"(d[2]), "+f"(d[3])
        : "r"(a[0]), "r"(a[1]), "r"(a[2]), "r"(a[3]), "r"(b[0]), "r"(b[1]));
}

// ---------------------------------------------------------------------------
// fp32 -> bf16 hi/lo split conversion (memory-bound elementwise)
// ---------------------------------------------------------------------------
__global__ __launch_bounds__(256) void cvt_hilo(const float4* __restrict__ src,
                                                __nv_bfloat162* __restrict__ hi,
                                                __nv_bfloat162* __restrict__ lo,
                                                int n4)
{
    int i = blockIdx.x * blockDim.x + threadIdx.x;
    if (i >= n4) return;
    float4 v = src[i];
    __nv_bfloat16 h0 = __float2bfloat16(v.x);
    __nv_bfloat16 h1 = __float2bfloat16(v.y);
    __nv_bfloat16 h2 = __float2bfloat16(v.z);
    __nv_bfloat16 h3 = __float2bfloat16(v.w);
    float l0 = v.x - __bfloat162float(h0);
    float l1 = v.y - __bfloat162float(h1);
    float l2 = v.z - __bfloat162float(h2);
    float l3 = v.w - __bfloat162float(h3);
    hi[2*i + 0] = __halves2bfloat162(h0, h1);
    hi[2*i + 1] = __halves2bfloat162(h2, h3);
    lo[2*i + 0] = __halves2bfloat162(__float2bfloat16(l0), __float2bfloat16(l1));
    lo[2*i + 1] = __halves2bfloat162(__float2bfloat16(l2), __float2bfloat16(l3));
}

// ---------------------------------------------------------------------------
// mma.sync bf16x3 GEMM:
//   C[m,n] = scale * sum_k (Ah+Al)[m,k]*(Bh+Bl)[n,k]   (lo*lo dropped)
// CTA tile 128x128, BK=32, cp.async double-buffered, 256 thr = 8 warps (2x4),
// warp tile 64x32, mma m16n8k16 row.col.
// LAYOUT 0: C row-major [M,1024]; LAYOUT 1: head-split scatter [B,H,S,DEPTH]
// ---------------------------------------------------------------------------
#define GK       1024
#define BKE      32
#define NSTG     (GK / BKE)          // 32
#define TPAD     40                  // row stride in halves (32 + 8 pad)
#define TILE_B   (128 * TPAD * 2)    // 10240 bytes per tile
#define STAGE_B  (4 * TILE_B)        // Ah, Al, Bh, Bl
#define GSMEM    (2 * STAGE_B)       // 81920 bytes

__device__ __forceinline__ void issue_stage(uint32_t sbase, int s, int k0, int m0, int n0,
                                            int tid,
                                            const __nv_bfloat16* Ah, const __nv_bfloat16* Al,
                                            const __nv_bfloat16* Bh, const __nv_bfloat16* Bl)
{
    const __nv_bfloat16* gsrc[4] = {Ah, Al, Bh, Bl};
    #pragma unroll
    for (int t = 0; t < 4; t++) {
        const int r0 = (t < 2) ? m0 : n0;
        const char* g = (const char*)(gsrc[t] + (size_t)r0 * GK + k0);
        uint32_t sb = sbase + s * STAGE_B + t * TILE_B;
        #pragma unroll
        for (int i = 0; i < 2; i++) {
            int slot = tid + i * 256;            // 0..511
            int row  = slot >> 2;                // 0..127
            int c16  = (slot & 3) * 16;          // byte offset in row (64B of data)
            cp_async16(sb + row * (TPAD * 2) + c16,
                       g + (size_t)row * (GK * 2) + c16);
        }
    }
}

template <int LAYOUT>
__global__ __launch_bounds__(256) void gemm_bf16x3(
    const __nv_bfloat16* __restrict__ Ah, const __nv_bfloat16* __restrict__ Al,
    const __nv_bfloat16* __restrict__ Bh, const __nv_bfloat16* __restrict__ Bl,
    float* __restrict__ C, float scale)
{
    extern __shared__ __align__(128) char smem[];
    const int tid = threadIdx.x;
    const int wid = tid >> 5;
    const int lane = tid & 31;
    const int warp_m = wid >> 2;      // 0..1  -> 64 rows each
    const int warp_n = wid & 3;       // 0..3  -> 32 cols each
    const int m0 = blockIdx.y * 128;
    const int n0 = blockIdx.x * 128;

    const uint32_t sbase = smem_u32(smem);

    float d[4][4][4];
    #pragma unroll
    for (int mf = 0; mf < 4; mf++)
        #pragma unroll
        for (int nf = 0; nf < 4; nf++)
            #pragma unroll
            for (int r = 0; r < 4; r++) d[mf][nf][r] = 0.f;

    // ldmatrix lane addressing (fixed per thread)
    const int arow = warp_m * 64 + (lane & 15);
    const int acol8 = (lane >> 4) * 8;
    const int brow = warp_n * 32 + (lane & 7);
    const int bcol8 = ((lane >> 3) & 1) * 8;

    // preload stage 0
    issue_stage(sbase, 0, 0, m0, n0, tid, Ah, Al, Bh, Bl);
    cp_commit();

    for (int it = 0; it < NSTG; it++) {
        const int s = it & 1;
        if (it + 1 < NSTG) {
            issue_stage(sbase, s ^ 1, (it + 1) * BKE, m0, n0, tid, Ah, Al, Bh, Bl);
            cp_commit();
            cp_wait<1>();
        } else {
            cp_wait<0>();
        }
        __syncthreads();

        const uint32_t As_h = sbase + s * STAGE_B;
        const uint32_t As_l = As_h + TILE_B;
        const uint32_t Bs_h = As_h + 2 * TILE_B;
        const uint32_t Bs_l = As_h + 3 * TILE_B;

        #pragma unroll
        for (int ks = 0; ks < 2; ks++) {          // two k16 steps in BK=32
            const int kb = ks * 16;
            uint32_t ah[4][4], al[4][4], bh[4][2], bl[4][2];
            #pragma unroll
            for (int mf = 0; mf < 4; mf++) {
                uint32_t off = (uint32_t)((arow + mf * 16) * TPAD + kb + acol8) * 2;
                ldmx4(ah[mf], As_h + off);
                ldmx4(al[mf], As_l + off);
            }
            #pragma unroll
            for (int nf = 0; nf < 4; nf++) {
                uint32_t off = (uint32_t)((brow + nf * 8) * TPAD + kb + bcol8) * 2;
                ldmx2(bh[nf], Bs_h + off);
                ldmx2(bl[nf], Bs_l + off);
            }
            #pragma unroll
            for (int mf = 0; mf < 4; mf++)
                #pragma unroll
                for (int nf = 0; nf < 4; nf++) {
                    mma16816(d[mf][nf], ah[mf], bh[nf]);
                    mma16816(d[mf][nf], ah[mf], bl[nf]);
                    mma16816(d[mf][nf], al[mf], bh[nf]);
                }
        }
        __syncthreads();
    }

    // Epilogue: d-fragment mapping: rows g=lane>>2 (+8), cols 2*(lane&3) (+1)
    const int g = lane >> 2;
    const int tg = lane & 3;
    #pragma unroll
    for (int mf = 0; mf < 4; mf++) {
        #pragma unroll
        for (int nf = 0; nf < 4; nf++) {
            int m = m0 + warp_m * 64 + mf * 16 + g;
            int n = n0 + warp_n * 32 + nf * 8 + tg * 2;
            #pragma unroll
            for (int half = 0; half < 2; half++) {   // rows g and g+8
                float2 v;
                v.x = d[mf][nf][half * 2 + 0] * scale;
                v.y = d[mf][nf][half * 2 + 1] * scale;
                int mm = m + half * 8;
                if (LAYOUT == 0) {
                    *(float2*)&C[(size_t)mm * DMODEL + n] = v;
                } else {
                    int b = mm >> 11;
                    int sI = mm & (SEQ - 1);
                    int h = n >> 6;
                    int dd = n & (DEPTH - 1);
                    *(float2*)&C[(((size_t)(b * NH + h)) * SEQ + sI) * DEPTH + dd] = v;
                }
            }
        }
    }
}

// ---------------------------------------------------------------------------
// Flash attention (fp32, online softmax) — unchanged from passing R2 kernel.
// ---------------------------------------------------------------------------
__global__ __launch_bounds__(256) void flash_kernel(const float* __restrict__ bias)
{
    extern __shared__ float sm[];
    float* Qt = sm;                    // 64*132
    float* Kt = Qt + 64 * 132;         // 64*68
    float* Vs = Kt + 64 * 68;          // 64*68
    float* Pt = Vs + 64 * 68;          // 64*132

    const int bh = blockIdx.x;
    const int q0 = blockIdx.y * 128;
    const int b  = bh >> 4;
    const int h  = bh & 15;

    const float* qbase = g_q + (size_t)bh * SEQ * DEPTH;
    const float* kbase = g_k + (size_t)bh * SEQ * DEPTH;
    const float* vbase = g_v + (size_t)bh * SEQ * DEPTH;

    const int tid = threadIdx.x;
    const int tx = tid & 15;
    const int ty = tid >> 4;
    const int r0 = ty * 8;
    const int c0 = tx * 4;

    #pragma unroll
    for (int i = 0; i < 8; i++) {
        int slot = tid + i * 256;
        int row = slot >> 4;
        int c4  = (slot & 15) * 4;
        float4 v = *(const float4*)&qbase[(size_t)(q0 + row) * DEPTH + c4];
        Qt[(c4 + 0) * 132 + row] = v.x;
        Qt[(c4 + 1) * 132 + row] = v.y;
        Qt[(c4 + 2) * 132 + row] = v.z;
        Qt[(c4 + 3) * 132 + row] = v.w;
    }

    float o[8][4];
    float mrow[8], lrow[8];
    #pragma unroll
    for (int i = 0; i < 8; i++) {
        mrow[i] = -INFINITY;
        lrow[i] = 0.f;
        #pragma unroll
        for (int j = 0; j < 4; j++) o[i][j] = 0.f;
    }

    for (int k0 = 0; k0 < SEQ; k0 += 64) {
        __syncthreads();
        #pragma unroll
        for (int i = 0; i < 4; i++) {
            int slot = tid + i * 256;
            int row = slot >> 4;
            int c4  = (slot & 15) * 4;
            float4 kv = *(const float4*)&kbase[(size_t)(k0 + row) * DEPTH + c4];
            Kt[(c4 + 0) * 68 + row] = kv.x;
            Kt[(c4 + 1) * 68 + row] = kv.y;
            Kt[(c4 + 2) * 68 + row] = kv.z;
            Kt[(c4 + 3) * 68 + row] = kv.w;
            float4 vv = *(const float4*)&vbase[(size_t)(k0 + row) * DEPTH + c4];
            *(float4*)&Vs[row * 68 + c4] = vv;
        }
        __syncthreads();

        float s[8][4];
        #pragma unroll
        for (int i = 0; i < 8; i++)
            #pragma unroll
            for (int j = 0; j < 4; j++) s[i][j] = 0.f;

        #pragma unroll
        for (int d = 0; d < 64; d++) {
            float a[8], kk[4];
            *(float4*)&a[0] = *(const float4*)&Qt[d * 132 + r0];
            *(float4*)&a[4] = *(const float4*)&Qt[d * 132 + r0 + 4];
            *(float4*)&kk[0] = *(const float4*)&Kt[d * 68 + c0];
            #pragma unroll
            for (int i = 0; i < 8; i++)
                #pragma unroll
                for (int j = 0; j < 4; j++)
                    s[i][j] = fmaf(a[i], kk[j], s[i][j]);
        }

        #pragma unroll
        for (int i = 0; i < 8; i++) {
            float4 bv = *(const float4*)&bias[(size_t)(q0 + r0 + i) * SEQ + k0 + c0];
            s[i][0] += bv.x; s[i][1] += bv.y; s[i][2] += bv.z; s[i][3] += bv.w;
        }

        #pragma unroll
        for (int i = 0; i < 8; i++) {
            float tmax = s[i][0];
            tmax = fmaxf(tmax, s[i][1]);
            tmax = fmaxf(tmax, s[i][2]);
            tmax = fmaxf(tmax, s[i][3]);
            #pragma unroll
            for (int off = 1; off < 16; off <<= 1)
                tmax = fmaxf(tmax, __shfl_xor_sync(0xffffffffu, tmax, off));
            float mnew = fmaxf(mrow[i], tmax);
            float corr = __expf(mrow[i] - mnew);
            float rs = 0.f;
            #pragma unroll
            for (int j = 0; j < 4; j++) {
                s[i][j] = __expf(s[i][j] - mnew);
                rs += s[i][j];
            }
            #pragma unroll
            for (int off = 1; off < 16; off <<= 1)
                rs += __shfl_xor_sync(0xffffffffu, rs, off);
            lrow[i] = lrow[i] * corr + rs;
            mrow[i] = mnew;
            #pragma unroll
            for (int j = 0; j < 4; j++) o[i][j] *= corr;
            #pragma unroll
            for (int j = 0; j < 4; j++)
                Pt[(c0 + j) * 132 + r0 + i] = s[i][j];
        }
        __syncthreads();

        #pragma unroll
        for (int k = 0; k < 64; k++) {
            float p[8], vv[4];
            *(float4*)&p[0] = *(const float4*)&Pt[k * 132 + r0];
            *(float4*)&p[4] = *(const float4*)&Pt[k * 132 + r0 + 4];
            *(float4*)&vv[0] = *(const float4*)&Vs[k * 68 + c0];
            #pragma unroll
            for (int i = 0; i < 8; i++)
                #pragma unroll
                for (int j = 0; j < 4; j++)
                    o[i][j] = fmaf(p[i], vv[j], o[i][j]);
        }
    }

    #pragma unroll
    for (int i = 0; i < 8; i++) {
        float inv = 1.f / lrow[i];
        float4 v;
        v.x = o[i][0] * inv;
        v.y = o[i][1] * inv;
        v.z = o[i][2] * inv;
        v.w = o[i][3] * inv;
        *(float4*)&g_attn[((size_t)b * SEQ + q0 + r0 + i) * DMODEL + h * DEPTH + c0] = v;
    }
}

// ---------------------------------------------------------------------------
// Launch
// ---------------------------------------------------------------------------
extern "C" void kernel_launch(void* const* d_in, const int* in_sizes, int n_in,
                              void* d_out, int out_size)
{
    const float* x    = (const float*)d_in[0];
    const float* y    = (const float*)d_in[1];
    const float* bias = (const float*)d_in[2];
    const float* Wq   = (const float*)d_in[3];
    const float* Wk   = (const float*)d_in[4];
    const float* Wv   = (const float*)d_in[5];
    const float* Wo   = (const float*)d_in[6];
    float* out = (float*)d_out;

    float* dq; cudaGetSymbolAddress((void**)&dq, g_q);
    float* dk; cudaGetSymbolAddress((void**)&dk, g_k);
    float* dv; cudaGetSymbolAddress((void**)&dv, g_v);
    float* da; cudaGetSymbolAddress((void**)&da, g_attn);

    unsigned short *xh, *xl, *yh, *yl, *ah, *al;
    unsigned short *wqh, *wql, *wkh, *wkl, *wvh, *wvl, *woh, *wol;
    cudaGetSymbolAddress((void**)&xh, g_xh);   cudaGetSymbolAddress((void**)&xl, g_xl);
    cudaGetSymbolAddress((void**)&yh, g_yh);   cudaGetSymbolAddress((void**)&yl, g_yl);
    cudaGetSymbolAddress((void**)&ah, g_ah);   cudaGetSymbolAddress((void**)&al, g_al);
    cudaGetSymbolAddress((void**)&wqh, g_wqh); cudaGetSymbolAddress((void**)&wql, g_wql);
    cudaGetSymbolAddress((void**)&wkh, g_wkh); cudaGetSymbolAddress((void**)&wkl, g_wkl);
    cudaGetSymbolAddress((void**)&wvh, g_wvh); cudaGetSymbolAddress((void**)&wvl, g_wvl);
    cudaGetSymbolAddress((void**)&woh, g_woh); cudaGetSymbolAddress((void**)&wol, g_wol);

    const int flash_smem = (64*132 + 64*68 + 64*68 + 64*132) * (int)sizeof(float);
    cudaFuncSetAttribute(flash_kernel, cudaFuncAttributeMaxDynamicSharedMemorySize, flash_smem);
    cudaFuncSetAttribute(gemm_bf16x3<0>, cudaFuncAttributeMaxDynamicSharedMemorySize, GSMEM);
    cudaFuncSetAttribute(gemm_bf16x3<1>, cudaFuncAttributeMaxDynamicSharedMemorySize, GSMEM);

    const int n4big = MROWS * DMODEL / 4;     // 2097152
    const int n4w   = DMODEL * DMODEL / 4;    // 262144

    cvt_hilo<<<n4big/256, 256>>>((const float4*)x, (__nv_bfloat162*)xh, (__nv_bfloat162*)xl, n4big);
    cvt_hilo<<<n4big/256, 256>>>((const float4*)y, (__nv_bfloat162*)yh, (__nv_bfloat162*)yl, n4big);
    cvt_hilo<<<n4w/256, 256>>>((const float4*)Wq, (__nv_bfloat162*)wqh, (__nv_bfloat162*)wql, n4w);
    cvt_hilo<<<n4w/256, 256>>>((const float4*)Wk, (__nv_bfloat162*)wkh, (__nv_bfloat162*)wkl, n4w);
    cvt_hilo<<<n4w/256, 256>>>((const float4*)Wv, (__nv_bfloat162*)wvh, (__nv_bfloat162*)wvl, n4w);
    cvt_hilo<<<n4w/256, 256>>>((const float4*)Wo, (__nv_bfloat162*)woh, (__nv_bfloat162*)wol, n4w);

    dim3 ggrid(DMODEL / 128, MROWS / 128);    // (8, 64)
    const float qscale = 0.125f;              // DEPTH^-0.5

    gemm_bf16x3<1><<<ggrid, 256, GSMEM>>>((const __nv_bfloat16*)xh, (const __nv_bfloat16*)xl,
                                          (const __nv_bfloat16*)wqh, (const __nv_bfloat16*)wql,
                                          dq, qscale);
    gemm_bf16x3<1><<<ggrid, 256, GSMEM>>>((const __nv_bfloat16*)yh, (const __nv_bfloat16*)yl,
                                          (const __nv_bfloat16*)wkh, (const __nv_bfloat16*)wkl,
                                          dk, 1.0f);
    gemm_bf16x3<1><<<ggrid, 256, GSMEM>>>((const __nv_bfloat16*)yh, (const __nv_bfloat16*)yl,
                                          (const __nv_bfloat16*)wvh, (const __nv_bfloat16*)wvl,
                                          dv, 1.0f);

    dim3 fgrid(BB * NH, SEQ / 128);           // (64, 16)
    flash_kernel<<<fgrid, dim3(256), flash_smem>>>(bias);

    cvt_hilo<<<n4big/256, 256>>>((const float4*)da, (__nv_bfloat162*)ah, (__nv_bfloat162*)al, n4big);
    gemm_bf16x3<0><<<ggrid, 256, GSMEM>>>((const __nv_bfloat16*)ah, (const __nv_bfloat16*)al,
                                          (const __nv_bfloat16*)woh, (const __nv_bfloat16*)wol,
                                          out, 1.0f);
}

// round 7
// speedup vs baseline: 2.4662x; 1.7130x over previous
#include <cuda_runtime.h>
#include <cuda_bf16.h>
#include <math.h>
#include <stdint.h>

// Problem constants
#define BB     4
#define SEQ    2048
#define DMODEL 1024
#define NH     16
#define DEPTH  64
#define MROWS  (BB*SEQ)   // 8192

// ---------------------------------------------------------------------------
// Scratch (static __device__ arrays — allocation-free per harness rules)
// All bf16 hi/lo pairs stored as ushort arrays.
// ---------------------------------------------------------------------------
__device__ unsigned short g_qh[BB*NH*SEQ*DEPTH], g_ql[BB*NH*SEQ*DEPTH];
__device__ unsigned short g_kh[BB*NH*SEQ*DEPTH], g_kl[BB*NH*SEQ*DEPTH];
__device__ unsigned short g_vh[BB*NH*SEQ*DEPTH], g_vl[BB*NH*SEQ*DEPTH];
__device__ unsigned short g_ah[MROWS*DMODEL],    g_al[MROWS*DMODEL];
__device__ unsigned short g_xh[MROWS*DMODEL],    g_xl[MROWS*DMODEL];
__device__ unsigned short g_yh[MROWS*DMODEL],    g_yl[MROWS*DMODEL];
__device__ unsigned short g_wqh[DMODEL*DMODEL],  g_wql[DMODEL*DMODEL];
__device__ unsigned short g_wkh[DMODEL*DMODEL],  g_wkl[DMODEL*DMODEL];
__device__ unsigned short g_wvh[DMODEL*DMODEL],  g_wvl[DMODEL*DMODEL];
__device__ unsigned short g_woh[DMODEL*DMODEL],  g_wol[DMODEL*DMODEL];

// ---------------------------------------------------------------------------
// Baseline-PTX helpers (no tcgen05 — harness compiles for compute_103!)
// ---------------------------------------------------------------------------
__device__ __forceinline__ uint32_t smem_u32(const void* p) {
    uint32_t r;
    asm("{ .reg .u64 t; cvta.to.shared.u64 t, %1; cvt.u32.u64 %0, t; }"
        : "=r"(r) : "l"(p));
    return r;
}
__device__ __forceinline__ void cp_async16(uint32_t saddr, const void* gaddr) {
    asm volatile("cp.async.cg.shared.global [%0], [%1], 16;"
                 :: "r"(saddr), "l"(gaddr) : "memory");
}
__device__ __forceinline__ void cp_commit() {
    asm volatile("cp.async.commit_group;" ::: "memory");
}
template <int N>
__device__ __forceinline__ void cp_wait() {
    asm volatile("cp.async.wait_group %0;" :: "n"(N) : "memory");
}
__device__ __forceinline__ void ldmx4(uint32_t* r, uint32_t a) {
    asm volatile("ldmatrix.sync.aligned.m8n8.x4.shared.b16 {%0,%1,%2,%3}, [%4];"
                 : "=r"(r[0]), "=r"(r[1]), "=r"(r[2]), "=r"(r[3]) : "r"(a));
}
__device__ __forceinline__ void ldmx2(uint32_t* r, uint32_t a) {
    asm volatile("ldmatrix.sync.aligned.m8n8.x2.shared.b16 {%0,%1}, [%2];"
                 : "=r"(r[0]), "=r"(r[1]) : "r"(a));
}
__device__ __forceinline__ void ldmx4t(uint32_t* r, uint32_t a) {
    asm volatile("ldmatrix.sync.aligned.m8n8.x4.trans.shared.b16 {%0,%1,%2,%3}, [%4];"
                 : "=r"(r[0]), "=r"(r[1]), "=r"(r[2]), "=r"(r[3]) : "r"(a));
}
__device__ __forceinline__ void mma16816(float* d, const uint32_t* a, const uint32_t* b) {
    asm volatile(
        "mma.sync.aligned.m16n8k16.row.col.f32.bf16.bf16.f32 "
        "{%0,%1,%2,%3}, {%4,%5,%6,%7}, {%8,%9}, {%0,%1,%2,%3};"
        : "+f"(d[0]), "+f"(d[1]), "+f"(d[2]), "+f"(d[3])
        : "r"(a[0]), "r"(a[1]), "r"(a[2]), "r"(a[3]), "r"(b[0]), "r"(b[1]));
}

// Split a float pair into bf16 hi/lo packed b32s (low half = first value)
__device__ __forceinline__ void pack_hilo(float f0, float f1, uint32_t& h, uint32_t& l) {
    __nv_bfloat162 hb = __floats2bfloat162_rn(f0, f1);
    uint32_t hu = *reinterpret_cast<uint32_t*>(&hb);
    float r0 = f0 - __int_as_float(hu << 16);
    float r1 = f1 - __int_as_float(hu & 0xFFFF0000u);
    __nv_bfloat162 lb = __floats2bfloat162_rn(r0, r1);
    h = hu;
    l = *reinterpret_cast<uint32_t*>(&lb);
}

// FMA-pipe 2^t (t <= 0 in all our uses). deg-5 Taylor on [-0.5,0.5], err ~2.4e-6.
__device__ __forceinline__ float exp2p(float t) {
    t = fmaxf(t, -126.f);
    float z = t + 12582912.f;          // 1.5*2^23 round-to-int trick
    float n = z - 12582912.f;
    float f = t - n;
    float p = 0.0013333558f;
    p = fmaf(p, f, 0.0096181291f);
    p = fmaf(p, f, 0.0555041087f);
    p = fmaf(p, f, 0.2402265070f);
    p = fmaf(p, f, 0.6931471806f);
    p = fmaf(p, f, 1.0f);
    int e = (__float_as_int(z) + (127 - 0x4B400000)) << 23;
    return __int_as_float(e) * p;
}

#define L2E 1.4426950408889634f

// ---------------------------------------------------------------------------
// fp32 -> bf16 hi/lo split conversion
// ---------------------------------------------------------------------------
__global__ __launch_bounds__(256) void cvt_hilo(const float4* __restrict__ src,
                                                __nv_bfloat162* __restrict__ hi,
                                                __nv_bfloat162* __restrict__ lo,
                                                int n4)
{
    int i = blockIdx.x * blockDim.x + threadIdx.x;
    if (i >= n4) return;
    float4 v = src[i];
    uint32_t h0, l0, h1, l1;
    pack_hilo(v.x, v.y, h0, l0);
    pack_hilo(v.z, v.w, h1, l1);
    hi[2*i + 0] = *reinterpret_cast<__nv_bfloat162*>(&h0);
    hi[2*i + 1] = *reinterpret_cast<__nv_bfloat162*>(&h1);
    lo[2*i + 0] = *reinterpret_cast<__nv_bfloat162*>(&l0);
    lo[2*i + 1] = *reinterpret_cast<__nv_bfloat162*>(&l1);
}

// ---------------------------------------------------------------------------
// mma.sync bf16x3 GEMM (validated in R6):
//   C[m,n] = scale * sum_k (Ah+Al)[m,k]*(Bh+Bl)[n,k]   (lo*lo dropped)
// LAYOUT 0: C fp32 row-major [M,1024]
// LAYOUT 1: C emitted as bf16 hi/lo pairs scattered to head-split [B,H,S,DEPTH]
// ---------------------------------------------------------------------------
#define GK       1024
#define BKE      32
#define NSTG     (GK / BKE)          // 32
#define TPAD     40
#define TILE_B   (128 * TPAD * 2)    // 10240
#define STAGE_B  (4 * TILE_B)
#define GSMEM    (2 * STAGE_B)       // 81920

__device__ __forceinline__ void issue_stage(uint32_t sbase, int s, int k0, int m0, int n0,
                                            int tid,
                                            const __nv_bfloat16* Ah, const __nv_bfloat16* Al,
                                            const __nv_bfloat16* Bh, const __nv_bfloat16* Bl)
{
    const __nv_bfloat16* gsrc[4] = {Ah, Al, Bh, Bl};
    #pragma unroll
    for (int t = 0; t < 4; t++) {
        const int r0 = (t < 2) ? m0 : n0;
        const char* g = (const char*)(gsrc[t] + (size_t)r0 * GK + k0);
        uint32_t sb = sbase + s * STAGE_B + t * TILE_B;
        #pragma unroll
        for (int i = 0; i < 2; i++) {
            int slot = tid + i * 256;
            int row  = slot >> 2;
            int c16  = (slot & 3) * 16;
            cp_async16(sb + row * (TPAD * 2) + c16,
                       g + (size_t)row * (GK * 2) + c16);
        }
    }
}

template <int LAYOUT>
__global__ __launch_bounds__(256) void gemm_bf16x3(
    const __nv_bfloat16* __restrict__ Ah, const __nv_bfloat16* __restrict__ Al,
    const __nv_bfloat16* __restrict__ Bh, const __nv_bfloat16* __restrict__ Bl,
    float* __restrict__ C,
    unsigned short* __restrict__ Ch, unsigned short* __restrict__ Cl,
    float scale)
{
    extern __shared__ __align__(128) char smem[];
    const int tid = threadIdx.x;
    const int wid = tid >> 5;
    const int lane = tid & 31;
    const int warp_m = wid >> 2;
    const int warp_n = wid & 3;
    const int m0 = blockIdx.y * 128;
    const int n0 = blockIdx.x * 128;

    const uint32_t sbase = smem_u32(smem);

    float d[4][4][4];
    #pragma unroll
    for (int mf = 0; mf < 4; mf++)
        #pragma unroll
        for (int nf = 0; nf < 4; nf++)
            #pragma unroll
            for (int r = 0; r < 4; r++) d[mf][nf][r] = 0.f;

    const int arow = warp_m * 64 + (lane & 15);
    const int acol8 = (lane >> 4) * 8;
    const int brow = warp_n * 32 + (lane & 7);
    const int bcol8 = ((lane >> 3) & 1) * 8;

    issue_stage(sbase, 0, 0, m0, n0, tid, Ah, Al, Bh, Bl);
    cp_commit();

    for (int it = 0; it < NSTG; it++) {
        const int s = it & 1;
        if (it + 1 < NSTG) {
            issue_stage(sbase, s ^ 1, (it + 1) * BKE, m0, n0, tid, Ah, Al, Bh, Bl);
            cp_commit();
            cp_wait<1>();
        } else {
            cp_wait<0>();
        }
        __syncthreads();

        const uint32_t As_h = sbase + s * STAGE_B;
        const uint32_t As_l = As_h + TILE_B;
        const uint32_t Bs_h = As_h + 2 * TILE_B;
        const uint32_t Bs_l = As_h + 3 * TILE_B;

        #pragma unroll
        for (int ks = 0; ks < 2; ks++) {
            const int kb = ks * 16;
            uint32_t ah[4][4], al[4][4], bh[4][2], bl[4][2];
            #pragma unroll
            for (int mf = 0; mf < 4; mf++) {
                uint32_t off = (uint32_t)((arow + mf * 16) * TPAD + kb + acol8) * 2;
                ldmx4(ah[mf], As_h + off);
                ldmx4(al[mf], As_l + off);
            }
            #pragma unroll
            for (int nf = 0; nf < 4; nf++) {
                uint32_t off = (uint32_t)((brow + nf * 8) * TPAD + kb + bcol8) * 2;
                ldmx2(bh[nf], Bs_h + off);
                ldmx2(bl[nf], Bs_l + off);
            }
            #pragma unroll
            for (int mf = 0; mf < 4; mf++)
                #pragma unroll
                for (int nf = 0; nf < 4; nf++) {
                    mma16816(d[mf][nf], ah[mf], bh[nf]);
                    mma16816(d[mf][nf], ah[mf], bl[nf]);
                    mma16816(d[mf][nf], al[mf], bh[nf]);
                }
        }
        __syncthreads();
    }

    const int g = lane >> 2;
    const int tg = lane & 3;
    #pragma unroll
    for (int mf = 0; mf < 4; mf++) {
        #pragma unroll
        for (int nf = 0; nf < 4; nf++) {
            int m = m0 + warp_m * 64 + mf * 16 + g;
            int n = n0 + warp_n * 32 + nf * 8 + tg * 2;
            #pragma unroll
            for (int half = 0; half < 2; half++) {
                float vx = d[mf][nf][half * 2 + 0] * scale;
                float vy = d[mf][nf][half * 2 + 1] * scale;
                int mm = m + half * 8;
                if (LAYOUT == 0) {
                    float2 v; v.x = vx; v.y = vy;
                    *(float2*)&C[(size_t)mm * DMODEL + n] = v;
                } else {
                    uint32_t hp, lp;
                    pack_hilo(vx, vy, hp, lp);
                    int bI = mm >> 11;
                    int sI = mm & (SEQ - 1);
                    int hI = n >> 6;
                    int dd = n & (DEPTH - 1);
                    size_t idx = (((size_t)(bI * NH + hI)) * SEQ + sI) * DEPTH + dd;
                    *(uint32_t*)&Ch[idx] = hp;
                    *(uint32_t*)&Cl[idx] = lp;
                }
            }
        }
    }
}

// ---------------------------------------------------------------------------
// Flash attention v2: mma.sync bf16x3 QK^T and PV + polynomial exp.
// CTA = 256 thr (8 warps), Br=128 (warp owns 16 q rows), Bc=64, depth 64.
// Smem: Q hi/lo [128][72] + double-buffered K/V hi/lo [64][72] tiles.
// ---------------------------------------------------------------------------
#define FPITCH 72                      // halves per row (64 + 8 pad)
#define FROWB  (FPITCH*2)              // 144 bytes
#define FQH    0
#define FQL    (128*FROWB)             // 18432
#define FKV0   (2*128*FROWB)           // 36864
#define FSTG   (4*64*FROWB)            // 36864
#define FKH    0
#define FKL    (64*FROWB)              // 9216
#define FVH    (2*64*FROWB)            // 18432
#define FVL    (3*64*FROWB)            // 27648
#define FSMEM  (FKV0 + 2*FSTG)         // 110592

__device__ __forceinline__ void flash_issue_kv(uint32_t sb, int kv0, int tid,
                                               const unsigned short* kh, const unsigned short* kl,
                                               const unsigned short* vh, const unsigned short* vl)
{
    const unsigned short* srcs[4] = {kh, kl, vh, vl};
    #pragma unroll
    for (int i = 0; i < 8; i++) {
        const int t = i >> 1;                 // compile-time per unrolled i
        int slot = (i & 1) * 256 + tid;       // 0..511
        int r = slot >> 3;                    // 0..63
        int c = slot & 7;
        cp_async16(sb + t * 9216 + r * 144 + c * 16,
                   (const char*)(srcs[t] + (size_t)(kv0 + r) * DEPTH) + c * 16);
    }
}

__global__ __launch_bounds__(256) void flash_v2(const float* __restrict__ bias)
{
    extern __shared__ __align__(128) char smem[];
    const uint32_t sbase = smem_u32(smem);

    const int bh = blockIdx.x;          // 0..63
    const int q0 = blockIdx.y * 128;
    const int b  = bh >> 4;
    const int h  = bh & 15;

    const size_t hb = (size_t)bh * SEQ * DEPTH;
    const unsigned short* qhp = g_qh + hb;
    const unsigned short* qlp = g_ql + hb;
    const unsigned short* khp = g_kh + hb;
    const unsigned short* klp = g_kl + hb;
    const unsigned short* vhp = g_vh + hb;
    const unsigned short* vlp = g_vl + hb;

    const int tid = threadIdx.x;
    const int W = tid >> 5;
    const int lane = tid & 31;
    const int g = lane >> 2;
    const int tg = lane & 3;

    // ---- preload Q (hi+lo, 128 rows each) ----
    {
        const unsigned short* src = (tid & 128) ? qlp : qhp;
        uint32_t dst = sbase + ((tid & 128) ? FQL : FQH);
        int row = tid & 127;
        #pragma unroll
        for (int c = 0; c < 8; c++)
            cp_async16(dst + row * 144 + c * 16,
                       (const char*)(src + (size_t)(q0 + row) * DEPTH) + c * 16);
    }
    cp_commit();
    flash_issue_kv(sbase + FKV0, 0, tid, khp, klp, vhp, vlp);
    cp_commit();

    float o[8][4];
    #pragma unroll
    for (int nf = 0; nf < 8; nf++)
        #pragma unroll
        for (int r = 0; r < 4; r++) o[nf][r] = 0.f;
    float mrow[2] = {-INFINITY, -INFINITY};
    float lrow[2] = {0.f, 0.f};

    const uint32_t aoff = (uint32_t)((W * 16 + (lane & 15)) * FPITCH + ((lane >> 4) & 1) * 8) * 2;
    const uint32_t boff = (uint32_t)((lane & 7) * FPITCH + ((lane >> 3) & 1) * 8) * 2;

    for (int it = 0; it < SEQ / 64; it++) {
        const int s = it & 1;
        const int k0 = it * 64;
        if (it + 1 < SEQ / 64) {
            flash_issue_kv(sbase + FKV0 + (s ^ 1) * FSTG, (it + 1) * 64, tid,
                           khp, klp, vhp, vlp);
            cp_commit();
            cp_wait<1>();
        } else {
            cp_wait<0>();
        }
        __syncthreads();

        const uint32_t SB = sbase + FKV0 + s * FSTG;

        // ---- S = Q K^T (warp: 16 x 64), bf16x3 ----
        float sacc[8][4];
        #pragma unroll
        for (int nf = 0; nf < 8; nf++)
            #pragma unroll
            for (int r = 0; r < 4; r++) sacc[nf][r] = 0.f;

        uint32_t ah[4][4], al[4][4];
        #pragma unroll
        for (int ks = 0; ks < 4; ks++) {
            ldmx4(ah[ks], sbase + FQH + aoff + ks * 32);
            ldmx4(al[ks], sbase + FQL + aoff + ks * 32);
        }
        #pragma unroll
        for (int nf = 0; nf < 8; nf++) {
            const uint32_t bo = SB + (uint32_t)(nf * 8 * FPITCH * 2) + boff;
            #pragma unroll
            for (int ks = 0; ks < 4; ks++) {
                uint32_t kh2[2], kl2[2];
                ldmx2(kh2, bo + FKH + ks * 32);
                ldmx2(kl2, bo + FKL + ks * 32);
                mma16816(sacc[nf], ah[ks], kh2);
                mma16816(sacc[nf], ah[ks], kl2);
                mma16816(sacc[nf], al[ks], kh2);
            }
        }

        // ---- + bias ----
        {
            const float* bp = bias + (size_t)(q0 + W * 16 + g) * SEQ + k0 + tg * 2;
            #pragma unroll
            for (int nf = 0; nf < 8; nf++) {
                float2 b0 = *(const float2*)(bp + nf * 8);
                float2 b1 = *(const float2*)(bp + 8 * SEQ + nf * 8);
                sacc[nf][0] += b0.x; sacc[nf][1] += b0.y;
                sacc[nf][2] += b1.x; sacc[nf][3] += b1.y;
            }
        }

        // ---- online softmax (rows g and g+8; reduce over 4 tg lanes) ----
        #pragma unroll
        for (int r = 0; r < 2; r++) {
            float mx = fmaxf(sacc[0][2*r], sacc[0][2*r+1]);
            #pragma unroll
            for (int nf = 1; nf < 8; nf++)
                mx = fmaxf(mx, fmaxf(sacc[nf][2*r], sacc[nf][2*r+1]));
            mx = fmaxf(mx, __shfl_xor_sync(0xffffffffu, mx, 1));
            mx = fmaxf(mx, __shfl_xor_sync(0xffffffffu, mx, 2));
            float mnew = fmaxf(mrow[r], mx);
            float mL = mnew * L2E;
            float corr = exp2p(fmaf(mrow[r], L2E, -mL));
            float sum = 0.f;
            #pragma unroll
            for (int nf = 0; nf < 8; nf++) {
                float p0 = exp2p(fmaf(sacc[nf][2*r],   L2E, -mL));
                float p1 = exp2p(fmaf(sacc[nf][2*r+1], L2E, -mL));
                sacc[nf][2*r] = p0; sacc[nf][2*r+1] = p1;
                sum += p0 + p1;
            }
            sum += __shfl_xor_sync(0xffffffffu, sum, 1);
            sum += __shfl_xor_sync(0xffffffffu, sum, 2);
            lrow[r] = lrow[r] * corr + sum;
            mrow[r] = mnew;
            #pragma unroll
            for (int nf = 0; nf < 8; nf++) {
                o[nf][2*r]   *= corr;
                o[nf][2*r+1] *= corr;
            }
        }

        // ---- O += P V (P re-packed in-register to A-fragments, bf16x3) ----
        #pragma unroll
        for (int ks = 0; ks < 4; ks++) {
            uint32_t ph[4], pl[4];
            pack_hilo(sacc[2*ks][0],   sacc[2*ks][1],   ph[0], pl[0]);
            pack_hilo(sacc[2*ks][2],   sacc[2*ks][3],   ph[1], pl[1]);
            pack_hilo(sacc[2*ks+1][0], sacc[2*ks+1][1], ph[2], pl[2]);
            pack_hilo(sacc[2*ks+1][2], sacc[2*ks+1][3], ph[3], pl[3]);
            const uint32_t vro = (uint32_t)((ks * 16 + (lane & 15)) * FPITCH) * 2;
            #pragma unroll
            for (int nfp = 0; nfp < 4; nfp++) {
                uint32_t voff = vro + (uint32_t)((nfp * 2 + ((lane >> 4) & 1)) * 8) * 2;
                uint32_t vh4[4], vl4[4];
                ldmx4t(vh4, SB + FVH + voff);
                ldmx4t(vl4, SB + FVL + voff);
                mma16816(o[nfp*2],     ph, vh4);
                mma16816(o[nfp*2],     ph, vl4);
                mma16816(o[nfp*2],     pl, vh4);
                mma16816(o[nfp*2 + 1], ph, vh4 + 2);
                mma16816(o[nfp*2 + 1], ph, vl4 + 2);
                mma16816(o[nfp*2 + 1], pl, vh4 + 2);
            }
        }
        __syncthreads();
    }

    // ---- epilogue: normalize, emit bf16 hi/lo attn in [B,S,D] layout ----
    const float inv0 = 1.0f / lrow[0];
    const float inv1 = 1.0f / lrow[1];
    const int mr = q0 + W * 16 + g;
    #pragma unroll
    for (int nf = 0; nf < 8; nf++) {
        int col = h * DEPTH + nf * 8 + tg * 2;
        uint32_t hp, lp;
        pack_hilo(o[nf][0] * inv0, o[nf][1] * inv0, hp, lp);
        size_t i0 = ((size_t)b * SEQ + mr) * DMODEL + col;
        *(uint32_t*)&g_ah[i0] = hp;
        *(uint32_t*)&g_al[i0] = lp;
        pack_hilo(o[nf][2] * inv1, o[nf][3] * inv1, hp, lp);
        size_t i1 = ((size_t)b * SEQ + mr + 8) * DMODEL + col;
        *(uint32_t*)&g_ah[i1] = hp;
        *(uint32_t*)&g_al[i1] = lp;
    }
}

// ---------------------------------------------------------------------------
// Launch
// ---------------------------------------------------------------------------
extern "C" void kernel_launch(void* const* d_in, const int* in_sizes, int n_in,
                              void* d_out, int out_size)
{
    const float* x    = (const float*)d_in[0];
    const float* y    = (const float*)d_in[1];
    const float* bias = (const float*)d_in[2];
    const float* Wq   = (const float*)d_in[3];
    const float* Wk   = (const float*)d_in[4];
    const float* Wv   = (const float*)d_in[5];
    const float* Wo   = (const float*)d_in[6];
    float* out = (float*)d_out;

    unsigned short *qh, *ql, *kh, *kl, *vh, *vl, *ah, *al;
    unsigned short *xh, *xl, *yh, *yl;
    unsigned short *wqh, *wql, *wkh, *wkl, *wvh, *wvl, *woh, *wol;
    cudaGetSymbolAddress((void**)&qh, g_qh);   cudaGetSymbolAddress((void**)&ql, g_ql);
    cudaGetSymbolAddress((void**)&kh, g_kh);   cudaGetSymbolAddress((void**)&kl, g_kl);
    cudaGetSymbolAddress((void**)&vh, g_vh);   cudaGetSymbolAddress((void**)&vl, g_vl);
    cudaGetSymbolAddress((void**)&ah, g_ah);   cudaGetSymbolAddress((void**)&al, g_al);
    cudaGetSymbolAddress((void**)&xh, g_xh);   cudaGetSymbolAddress((void**)&xl, g_xl);
    cudaGetSymbolAddress((void**)&yh, g_yh);   cudaGetSymbolAddress((void**)&yl, g_yl);
    cudaGetSymbolAddress((void**)&wqh, g_wqh); cudaGetSymbolAddress((void**)&wql, g_wql);
    cudaGetSymbolAddress((void**)&wkh, g_wkh); cudaGetSymbolAddress((void**)&wkl, g_wkl);
    cudaGetSymbolAddress((void**)&wvh, g_wvh); cudaGetSymbolAddress((void**)&wvl, g_wvl);
    cudaGetSymbolAddress((void**)&woh, g_woh); cudaGetSymbolAddress((void**)&wol, g_wol);

    cudaFuncSetAttribute(gemm_bf16x3<0>, cudaFuncAttributeMaxDynamicSharedMemorySize, GSMEM);
    cudaFuncSetAttribute(gemm_bf16x3<1>, cudaFuncAttributeMaxDynamicSharedMemorySize, GSMEM);
    cudaFuncSetAttribute(flash_v2, cudaFuncAttributeMaxDynamicSharedMemorySize, FSMEM);

    const int n4big = MROWS * DMODEL / 4;
    const int n4w   = DMODEL * DMODEL / 4;

    cvt_hilo<<<n4big/256, 256>>>((const float4*)x, (__nv_bfloat162*)xh, (__nv_bfloat162*)xl, n4big);
    cvt_hilo<<<n4big/256, 256>>>((const float4*)y, (__nv_bfloat162*)yh, (__nv_bfloat162*)yl, n4big);
    cvt_hilo<<<n4w/256, 256>>>((const float4*)Wq, (__nv_bfloat162*)wqh, (__nv_bfloat162*)wql, n4w);
    cvt_hilo<<<n4w/256, 256>>>((const float4*)Wk, (__nv_bfloat162*)wkh, (__nv_bfloat162*)wkl, n4w);
    cvt_hilo<<<n4w/256, 256>>>((const float4*)Wv, (__nv_bfloat162*)wvh, (__nv_bfloat162*)wvl, n4w);
    cvt_hilo<<<n4w/256, 256>>>((const float4*)Wo, (__nv_bfloat162*)woh, (__nv_bfloat162*)wol, n4w);

    dim3 ggrid(DMODEL / 128, MROWS / 128);    // (8, 64)
    const float qscale = 0.125f;

    gemm_bf16x3<1><<<ggrid, 256, GSMEM>>>((const __nv_bfloat16*)xh, (const __nv_bfloat16*)xl,
                                          (const __nv_bfloat16*)wqh, (const __nv_bfloat16*)wql,
                                          nullptr, qh, ql, qscale);
    gemm_bf16x3<1><<<ggrid, 256, GSMEM>>>((const __nv_bfloat16*)yh, (const __nv_bfloat16*)yl,
                                          (const __nv_bfloat16*)wkh, (const __nv_bfloat16*)wkl,
                                          nullptr, kh, kl, 1.0f);
    gemm_bf16x3<1><<<ggrid, 256, GSMEM>>>((const __nv_bfloat16*)yh, (const __nv_bfloat16*)yl,
                                          (const __nv_bfloat16*)wvh, (const __nv_bfloat16*)wvl,
                                          nullptr, vh, vl, 1.0f);

    dim3 fgrid(BB * NH, SEQ / 128);           // (64, 16)
    flash_v2<<<fgrid, dim3(256), FSMEM>>>(bias);

    gemm_bf16x3<0><<<ggrid, 256, GSMEM>>>((const __nv_bfloat16*)ah, (const __nv_bfloat16*)al,
                                          (const __nv_bfloat16*)woh, (const __nv_bfloat16*)wol,
                                          out, nullptr, nullptr, 1.0f);
}